// round 16
// baseline (speedup 1.0000x reference)
#include <cuda_runtime.h>
#include <cuda_bf16.h>
#include <cstdint>

#define B_   4
#define T_   4096
#define C_   256
#define NTOK (B_ * T_)   // 16384

typedef __nv_bfloat16 bf16;

// ---------------- scratch (static device arrays; no allocation) --------------
__device__ bf16  g_gn[NTOK * C_];
__device__ bf16  g_wq[C_ * C_], g_wk[C_ * C_], g_wv[C_ * C_];
__device__ bf16  g_q [NTOK * C_];
__device__ bf16  g_k [NTOK * C_];
__device__ bf16  g_v [NTOK * C_];
__device__ bf16  g_e [(size_t)B_ * T_ * T_];   // E: [b][t][s] natural
__device__ bf16  g_vp[NTOK * C_];              // V': [b][t][c] = V/Z_t
__device__ float g_zpart[32 * NTOK];           // [s_tile][token]

// ---------------- helpers ------------------------------------------------------
__device__ __forceinline__ uint32_t smem_u32(const void* p) {
    uint32_t a;
    asm("{ .reg .u64 t; cvta.to.shared.u64 t, %1; cvt.u32.u64 %0, t; }" : "=r"(a) : "l"(p));
    return a;
}
__device__ __forceinline__ void cp16(uint32_t dst, const void* src) {
    asm volatile("cp.async.cg.shared.global [%0], [%1], 16;" :: "r"(dst), "l"(src));
}
__device__ __forceinline__ void cp_commit() {
    asm volatile("cp.async.commit_group;" ::: "memory");
}
template <int N> __device__ __forceinline__ void cp_wait() {
    asm volatile("cp.async.wait_group %0;" :: "n"(N) : "memory");
}
__device__ __forceinline__ void mma_bf16(float c[4],
                                         uint32_t a0, uint32_t a1, uint32_t a2, uint32_t a3,
                                         uint32_t b0, uint32_t b1) {
    asm volatile(
        "mma.sync.aligned.m16n8k16.row.col.f32.bf16.bf16.f32 "
        "{%0,%1,%2,%3}, {%4,%5,%6,%7}, {%8,%9}, {%0,%1,%2,%3};"
        : "+f"(c[0]), "+f"(c[1]), "+f"(c[2]), "+f"(c[3])
        : "r"(a0), "r"(a1), "r"(a2), "r"(a3), "r"(b0), "r"(b1));
}
__device__ __forceinline__ void ldsm4(uint32_t& r0, uint32_t& r1, uint32_t& r2, uint32_t& r3,
                                      uint32_t addr) {
    asm volatile("ldmatrix.sync.aligned.m8n8.x4.shared.b16 {%0,%1,%2,%3}, [%4];"
                 : "=r"(r0), "=r"(r1), "=r"(r2), "=r"(r3) : "r"(addr));
}
__device__ __forceinline__ void ldsm4t(uint32_t& r0, uint32_t& r1, uint32_t& r2, uint32_t& r3,
                                       uint32_t addr) {
    asm volatile("ldmatrix.sync.aligned.m8n8.x4.trans.shared.b16 {%0,%1,%2,%3}, [%4];"
                 : "=r"(r0), "=r"(r1), "=r"(r2), "=r"(r3) : "r"(addr));
}
__device__ __forceinline__ void stsm4(uint32_t addr, uint32_t r0, uint32_t r1,
                                      uint32_t r2, uint32_t r3) {
    asm volatile("stmatrix.sync.aligned.m8n8.x4.shared.b16 [%0], {%1,%2,%3,%4};"
                 :: "r"(addr), "r"(r0), "r"(r1), "r"(r2), "r"(r3) : "memory");
}
__device__ __forceinline__ float ex2(float x) {
    float y; asm("ex2.approx.f32 %0, %1;" : "=f"(y) : "f"(x)); return y;
}
__device__ __forceinline__ uint32_t pack_bf16(float a, float b) {
    uint32_t lo = __bfloat16_as_ushort(__float2bfloat16(a));
    uint32_t hi = __bfloat16_as_ushort(__float2bfloat16(b));
    return lo | (hi << 16);
}

// ---- scores/qkv smem ([rows][72 bf16], 144 B stride) ------------------------
#define BOFF  18432u
#define STG   36864u
#define DSM2  73728
// ---- av smem: two [64 k][136 u16] tiles (272 B stride), 2 stages ------------
#define AV_VOFF  17408u
#define AV_STG   34816u
#define AV_DSM   69632

// exp(x/16) = 2^(x * 0.0625*log2(e))
#define EXP_SCALE 0.09016844f

// ======== fused LayerNorm (blocks 0..2047) + weight conv (blocks 2048+) ======
__global__ void __launch_bounds__(256) ln_wconv_kernel(const float* __restrict__ x,
                                                       const float* __restrict__ gamma,
                                                       const float* __restrict__ beta,
                                                       const float* __restrict__ Wq,
                                                       const float* __restrict__ Wk,
                                                       const float* __restrict__ Wv) {
    if (blockIdx.x >= NTOK / 8) {
        // weight conversion: 192 blocks, 64 per matrix
        int wb = blockIdx.x - NTOK / 8;
        int m  = wb >> 6;                 // 0..2
        const float* src = (m == 0) ? Wq : (m == 1) ? Wk : Wv;
        bf16* dst = (m == 0) ? g_wq : (m == 1) ? g_wk : g_wv;
        int i = ((wb & 63) * 256 + threadIdx.x) * 4;
        float4 v = *(const float4*)&src[i];
        *(uint2*)&dst[i] = make_uint2(pack_bf16(v.x, v.y), pack_bf16(v.z, v.w));
        return;
    }

    const int warp = threadIdx.x >> 5;
    const int lane = threadIdx.x & 31;
    const int t = blockIdx.x * 8 + warp;
    const int c = lane * 8;
    const float* xr = x + (size_t)t * C_;

    float4 v0 = *(const float4*)&xr[c];
    float4 v1 = *(const float4*)&xr[c + 4];
    float s  = v0.x + v0.y + v0.z + v0.w + v1.x + v1.y + v1.z + v1.w;
    float sq = v0.x * v0.x + v0.y * v0.y + v0.z * v0.z + v0.w * v0.w
             + v1.x * v1.x + v1.y * v1.y + v1.z * v1.z + v1.w * v1.w;
    #pragma unroll
    for (int o = 16; o > 0; o >>= 1) {
        s  += __shfl_xor_sync(0xffffffffu, s,  o);
        sq += __shfl_xor_sync(0xffffffffu, sq, o);
    }
    float mu   = s * (1.f / C_);
    float var  = sq * (1.f / C_) - mu * mu;
    float rstd = rsqrtf(var + 1e-5f);

    float4 gm0 = *(const float4*)&gamma[c];
    float4 gm1 = *(const float4*)&gamma[c + 4];
    float4 bt0 = *(const float4*)&beta[c];
    float4 bt1 = *(const float4*)&beta[c + 4];

    uint4 o_;
    o_.x = pack_bf16((v0.x - mu) * rstd * gm0.x + bt0.x, (v0.y - mu) * rstd * gm0.y + bt0.y);
    o_.y = pack_bf16((v0.z - mu) * rstd * gm0.z + bt0.z, (v0.w - mu) * rstd * gm0.w + bt0.w);
    o_.z = pack_bf16((v1.x - mu) * rstd * gm1.x + bt1.x, (v1.y - mu) * rstd * gm1.y + bt1.y);
    o_.w = pack_bf16((v1.z - mu) * rstd * gm1.z + bt1.z, (v1.w - mu) * rstd * gm1.w + bt1.w);
    *(uint4*)&g_gn[(size_t)t * C_ + c] = o_;
}

// ====== QKV (bf16, 128 thr, 64x64 warp tiles, 2-stage single-sync) ===========
__global__ void __launch_bounds__(128, 3) qkv_kernel(const float* __restrict__ bq,
                                                     const float* __restrict__ bk,
                                                     const float* __restrict__ bv) {
    extern __shared__ char dsm[];
    const bf16* W; const float* bias; bf16* out;
    if (blockIdx.z == 0)      { W = g_wq; bias = bq; out = g_q; }
    else if (blockIdx.z == 1) { W = g_wk; bias = bk; out = g_k; }
    else                      { W = g_wv; bias = bv; out = g_v; }

    const int tid  = threadIdx.x;
    const int lane = tid & 31;
    const int wid  = tid >> 5;
    const int wm   = wid >> 1;
    const int wn   = wid & 1;
    const int m0   = blockIdx.x * 128;
    const int n0   = blockIdx.y * 128;

    float acc[4][8][4];
    #pragma unroll
    for (int mi = 0; mi < 4; mi++)
        #pragma unroll
        for (int ni = 0; ni < 8; ni++)
            #pragma unroll
            for (int r = 0; r < 4; r++) acc[mi][ni][r] = 0.f;

    const uint32_t sA = smem_u32(dsm);
    const uint32_t sB = sA + BOFF;

    const int arow = (lane & 7) + (lane & 8);
    const int acol = (lane & 16) ? 8 : 0;
    uint32_t aAddr[4];
    #pragma unroll
    for (int mi = 0; mi < 4; mi++)
        aAddr[mi] = sA + (uint32_t)(((wm * 64 + mi * 16 + arow) * 72 + acol) * 2);
    const int brow = (lane & 7) + ((lane & 16) ? 8 : 0);
    const int bcol = (lane & 8) ? 8 : 0;
    uint32_t bAddr[4];
    #pragma unroll
    for (int p = 0; p < 4; p++)
        bAddr[p] = sB + (uint32_t)(((wn * 64 + p * 16 + brow) * 72 + bcol) * 2);

    const int lrow = tid >> 3;          // 0..15
    const int lc8  = (tid & 7) * 8;

    auto issue_chunk = [&](int kc) {
        int kb = kc * 64;
        uint32_t so = (kc & 1) * STG;
        #pragma unroll
        for (int i = 0; i < 8; i++) {
            int row = lrow + i * 16;
            uint32_t d = so + (uint32_t)((row * 72 + lc8) * 2);
            cp16(sA + d, &g_gn[(size_t)(m0 + row) * C_ + kb + lc8]);
            cp16(sB + d, &W   [(size_t)(n0 + row) * C_ + kb + lc8]);
        }
        cp_commit();
    };

    issue_chunk(0);

    for (int kt = 0; kt < 4; kt++) {
        cp_wait<0>();
        __syncthreads();
        if (kt < 3) issue_chunk(kt + 1);

        const uint32_t so = (kt & 1) * STG;
        #pragma unroll
        for (int ks_i = 0; ks_i < 4; ks_i++) {
            const uint32_t koff = so + ks_i * 32;
            uint32_t a[4][4];
            #pragma unroll
            for (int mi = 0; mi < 4; mi++)
                ldsm4(a[mi][0], a[mi][1], a[mi][2], a[mi][3], aAddr[mi] + koff);
            #pragma unroll
            for (int p = 0; p < 4; p++) {
                uint32_t b0, b1, b2, b3;
                ldsm4(b0, b1, b2, b3, bAddr[p] + koff);
                #pragma unroll
                for (int mi = 0; mi < 4; mi++) {
                    mma_bf16(acc[mi][2 * p],     a[mi][0], a[mi][1], a[mi][2], a[mi][3], b0, b1);
                    mma_bf16(acc[mi][2 * p + 1], a[mi][0], a[mi][1], a[mi][2], a[mi][3], b2, b3);
                }
            }
        }
    }

    const int g = lane >> 2, tig = lane & 3;
    #pragma unroll
    for (int mi = 0; mi < 4; mi++) {
        int row = m0 + wm * 64 + mi * 16 + g;
        #pragma unroll
        for (int ni = 0; ni < 8; ni++) {
            int col = n0 + wn * 64 + ni * 8 + tig * 2;
            float2 bb = *(const float2*)&bias[col];
            *(uint32_t*)&out[(size_t)row * C_ + col] =
                pack_bf16(acc[mi][ni][0] + bb.x, acc[mi][ni][1] + bb.y);
            *(uint32_t*)&out[(size_t)(row + 8) * C_ + col] =
                pack_bf16(acc[mi][ni][2] + bb.x, acc[mi][ni][3] + bb.y);
        }
    }
}

// = scores (bf16, 128 thr, 64x64 warps, 1-sync) + ex2 + stmatrix E staging ====
__global__ void __launch_bounds__(128, 3) scores_kernel() {
    extern __shared__ char dsm[];
    __shared__ float rs[2][128];   // per-wn-half rowsums (no atomics)

    const int bz = blockIdx.z;
    const int t0 = blockIdx.x * 128;   // query rows
    const int s0 = blockIdx.y * 128;   // key cols
    const bf16* Q = g_q + (size_t)bz * T_ * C_;
    const bf16* K = g_k + (size_t)bz * T_ * C_;

    const int tid  = threadIdx.x;
    const int lane = tid & 31;
    const int wid  = tid >> 5;
    const int wm   = wid >> 1;
    const int wn   = wid & 1;

    float acc[4][8][4];
    #pragma unroll
    for (int mi = 0; mi < 4; mi++)
        #pragma unroll
        for (int ni = 0; ni < 8; ni++)
            #pragma unroll
            for (int r = 0; r < 4; r++) acc[mi][ni][r] = 0.f;

    const uint32_t sA = smem_u32(dsm);
    const uint32_t sB = sA + BOFF;

    const int arow = (lane & 7) + (lane & 8);
    const int acol = (lane & 16) ? 8 : 0;
    uint32_t aAddr[4];
    #pragma unroll
    for (int mi = 0; mi < 4; mi++)
        aAddr[mi] = sA + (uint32_t)(((wm * 64 + mi * 16 + arow) * 72 + acol) * 2);
    const int brow = (lane & 7) + ((lane & 16) ? 8 : 0);
    const int bcol = (lane & 8) ? 8 : 0;
    uint32_t bAddr[4];
    #pragma unroll
    for (int p = 0; p < 4; p++)
        bAddr[p] = sB + (uint32_t)(((wn * 64 + p * 16 + brow) * 72 + bcol) * 2);

    const int lrow = tid >> 3;          // 0..15
    const int lc8  = (tid & 7) * 8;

    auto issue_chunk = [&](int kc) {
        int kb = kc * 64;
        uint32_t so = (kc & 1) * STG;
        #pragma unroll
        for (int i = 0; i < 8; i++) {
            int row = lrow + i * 16;
            uint32_t d = so + (uint32_t)((row * 72 + lc8) * 2);
            cp16(sA + d, &Q[(size_t)(t0 + row) * C_ + kb + lc8]);
            cp16(sB + d, &K[(size_t)(s0 + row) * C_ + kb + lc8]);
        }
        cp_commit();
    };

    issue_chunk(0);

    for (int kt = 0; kt < 4; kt++) {
        cp_wait<0>();
        __syncthreads();
        if (kt < 3) issue_chunk(kt + 1);

        const uint32_t so = (kt & 1) * STG;
        #pragma unroll
        for (int ks_i = 0; ks_i < 4; ks_i++) {
            const uint32_t koff = so + ks_i * 32;
            uint32_t a[4][4];
            #pragma unroll
            for (int mi = 0; mi < 4; mi++)
                ldsm4(a[mi][0], a[mi][1], a[mi][2], a[mi][3], aAddr[mi] + koff);
            #pragma unroll
            for (int p = 0; p < 4; p++) {
                uint32_t b0, b1, b2, b3;
                ldsm4(b0, b1, b2, b3, bAddr[p] + koff);
                #pragma unroll
                for (int mi = 0; mi < 4; mi++) {
                    mma_bf16(acc[mi][2 * p],     a[mi][0], a[mi][1], a[mi][2], a[mi][3], b0, b1);
                    mma_bf16(acc[mi][2 * p + 1], a[mi][0], a[mi][1], a[mi][2], a[mi][3], b2, b3);
                }
            }
        }
    }

    const int g = lane >> 2, tig = lane & 3;

    // exp(score/16) via single-mul ex2
    #pragma unroll
    for (int mi = 0; mi < 4; mi++)
        #pragma unroll
        for (int ni = 0; ni < 8; ni++)
            #pragma unroll
            for (int r = 0; r < 4; r++)
                acc[mi][ni][r] = ex2(acc[mi][ni][r] * EXP_SCALE);

    // rowsums: rows disjoint per (wm, mi, g) within a wn-half -> plain stores
    #pragma unroll
    for (int mi = 0; mi < 4; mi++) {
        float s0v = 0.f, s1v = 0.f;
        #pragma unroll
        for (int ni = 0; ni < 8; ni++) {
            s0v += acc[mi][ni][0] + acc[mi][ni][1];
            s1v += acc[mi][ni][2] + acc[mi][ni][3];
        }
        s0v += __shfl_xor_sync(0xffffffffu, s0v, 1);
        s0v += __shfl_xor_sync(0xffffffffu, s0v, 2);
        s1v += __shfl_xor_sync(0xffffffffu, s1v, 1);
        s1v += __shfl_xor_sync(0xffffffffu, s1v, 2);
        if (tig == 0) {
            rs[wn][wm * 64 + mi * 16 + g]     = s0v;
            rs[wn][wm * 64 + mi * 16 + g + 8] = s1v;
        }
    }
    __syncthreads();   // mma/ldsm reads of dsm done + rowsums complete
    if (tid < 128)
        g_zpart[(size_t)blockIdx.y * NTOK + bz * T_ + t0 + tid] = rs[0][tid] + rs[1][tid];

    // stage NATURAL bf16 tile via stmatrix: et[t_local 128][s_local 136]
    unsigned short* et = (unsigned short*)dsm;
    const uint32_t etB = smem_u32(et);
    const int m4 = lane >> 3;
    const uint32_t laneRow = (uint32_t)((m4 & 1) * 8 + (lane & 7));
    const uint32_t laneColHalf = (uint32_t)((m4 >> 1) * 8);
    #pragma unroll
    for (int mi = 0; mi < 4; mi++) {
        uint32_t rowBase = (uint32_t)(wm * 64 + mi * 16) + laneRow;
        #pragma unroll
        for (int njp = 0; njp < 4; njp++) {
            int ni = 2 * njp;
            uint32_t col = (uint32_t)(wn * 64 + njp * 16) + laneColHalf;
            uint32_t addr = etB + (rowBase * 136 + col) * 2;
            stsm4(addr,
                  pack_bf16(acc[mi][ni][0],     acc[mi][ni][1]),
                  pack_bf16(acc[mi][ni][2],     acc[mi][ni][3]),
                  pack_bf16(acc[mi][ni + 1][0], acc[mi][ni + 1][1]),
                  pack_bf16(acc[mi][ni + 1][2], acc[mi][ni + 1][3]));
        }
    }
    __syncthreads();
    // coalesced store E[b][t0+tl][s0 .. s0+127]
    #pragma unroll
    for (int i = 0; i < 16; i++) {
        int lin = tid + i * 128;
        int tl = lin >> 4, c8 = (lin & 15) * 8;
        uint4 d = *(uint4*)&et[(size_t)tl * 136 + c8];
        *(uint4*)&g_e[(size_t)(bz * T_ + t0 + tl) * T_ + s0 + c8] = d;
    }
}

// == zv (fused Z-reduce): one warp per token; V'[t][c] = V[t][c] / Z_t ========
__global__ void __launch_bounds__(256) zv_kernel() {
    const int warp = threadIdx.x >> 5;
    const int lane = threadIdx.x & 31;
    const int tok  = blockIdx.x * 8 + warp;

    float s = g_zpart[(size_t)lane * NTOK + tok];
    #pragma unroll
    for (int o = 16; o > 0; o >>= 1) s += __shfl_xor_sync(0xffffffffu, s, o);
    float zi = 1.f / s;

    const int c = lane * 8;
    uint4 raw = *(const uint4*)&g_v[(size_t)tok * C_ + c];
    const unsigned short* u = (const unsigned short*)&raw;
    uint4 outv;
    unsigned short* o = (unsigned short*)&outv;
    #pragma unroll
    for (int j = 0; j < 8; j++) {
        float f = __bfloat162float(__ushort_as_bfloat16(u[j])) * zi;
        o[j] = __bfloat16_as_ushort(__float2bfloat16(f));
    }
    *(uint4*)&g_vp[(size_t)tok * C_ + c] = outv;
}

// == AV: out[s,c] = x + Σ_t E[t,s]·V'[t,c]; both operands trans-ldsm ==========
__global__ void __launch_bounds__(128, 3) av_kernel(const float* __restrict__ x,
                                                    float* __restrict__ out) {
    extern __shared__ char dsm[];
    const int bz = blockIdx.z;
    const int s0 = blockIdx.x * 128;
    const int c0 = blockIdx.y * 128;
    const bf16* Ea = g_e  + (size_t)bz * T_ * T_;   // [t][s]
    const bf16* Va = g_vp + (size_t)bz * T_ * C_;   // [t][c]

    const int tid  = threadIdx.x;
    const int lane = tid & 31;
    const int wid  = tid >> 5;
    const int wm   = wid >> 1;    // s-half
    const int wn   = wid & 1;     // c-half

    float acc[4][8][4];
    #pragma unroll
    for (int mi = 0; mi < 4; mi++)
        #pragma unroll
        for (int ni = 0; ni < 8; ni++)
            #pragma unroll
            for (int r = 0; r < 4; r++) acc[mi][ni][r] = 0.f;

    const uint32_t sE = smem_u32(dsm);
    const uint32_t sV = sE + AV_VOFF;

    const int atrow = (lane & 7) + ((lane & 16) ? 8 : 0);
    const int atcol = (lane & 8) ? 8 : 0;
    uint32_t aAddr[4];
    #pragma unroll
    for (int mi = 0; mi < 4; mi++)
        aAddr[mi] = sE + (uint32_t)((atrow * 136 + wm * 64 + mi * 16 + atcol) * 2);
    const int btrow = (lane & 7) + ((lane & 8) ? 8 : 0);
    const int btcol = (lane & 16) ? 8 : 0;
    uint32_t bAddr[4];
    #pragma unroll
    for (int p = 0; p < 4; p++)
        bAddr[p] = sV + (uint32_t)((btrow * 136 + wn * 64 + p * 16 + btcol) * 2);

    const int lrow = tid >> 4;          // 0..7
    const int lc16 = (tid & 15) * 16;   // byte col

    auto issue_chunk = [&](int kc) {
        int kb = kc * 64;
        uint32_t so = (kc & 1) * AV_STG;
        #pragma unroll
        for (int i = 0; i < 8; i++) {
            int r = lrow + i * 8;
            uint32_t d = so + (uint32_t)(r * 272 + lc16);
            cp16(sE + d, &Ea[(size_t)(kb + r) * T_ + s0 + (lc16 >> 1)]);
            cp16(sV + d, &Va[(size_t)(kb + r) * C_ + c0 + (lc16 >> 1)]);
        }
        cp_commit();
    };

    issue_chunk(0);

    const int KT = T_ / 64;   // 64
    for (int kt = 0; kt < KT; kt++) {
        cp_wait<0>();
        __syncthreads();
        if (kt < KT - 1) issue_chunk(kt + 1);

        const uint32_t so = (kt & 1) * AV_STG;
        #pragma unroll
        for (int ks_i = 0; ks_i < 4; ks_i++) {
            const uint32_t koff = so + ks_i * 16 * 272;   // 16 k-rows
            uint32_t a[4][4];
            #pragma unroll
            for (int mi = 0; mi < 4; mi++)
                ldsm4t(a[mi][0], a[mi][1], a[mi][2], a[mi][3], aAddr[mi] + koff);
            #pragma unroll
            for (int p = 0; p < 4; p++) {
                uint32_t b0, b1, b2, b3;
                ldsm4t(b0, b1, b2, b3, bAddr[p] + koff);
                #pragma unroll
                for (int mi = 0; mi < 4; mi++) {
                    mma_bf16(acc[mi][2 * p],     a[mi][0], a[mi][1], a[mi][2], a[mi][3], b0, b1);
                    mma_bf16(acc[mi][2 * p + 1], a[mi][0], a[mi][1], a[mi][2], a[mi][3], b2, b3);
                }
            }
        }
    }

    const int g = lane >> 2, tig = lane & 3;
    #pragma unroll
    for (int mi = 0; mi < 4; mi++) {
        int s = s0 + wm * 64 + mi * 16 + g;
        size_t base0 = ((size_t)bz * T_ + s) * C_;
        size_t base1 = ((size_t)bz * T_ + s + 8) * C_;
        #pragma unroll
        for (int ni = 0; ni < 8; ni++) {
            int c = c0 + wn * 64 + ni * 8 + tig * 2;
            float2 x0 = *(const float2*)&x[base0 + c];
            float2 x1 = *(const float2*)&x[base1 + c];
            *(float2*)&out[base0 + c] = make_float2(x0.x + acc[mi][ni][0], x0.y + acc[mi][ni][1]);
            *(float2*)&out[base1 + c] = make_float2(x1.x + acc[mi][ni][2], x1.y + acc[mi][ni][3]);
        }
    }
}

// ================================ launch =====================================
extern "C" void kernel_launch(void* const* d_in, const int* in_sizes, int n_in,
                              void* d_out, int out_size) {
    const float* x     = (const float*)d_in[0];
    const float* gamma = (const float*)d_in[1];
    const float* beta  = (const float*)d_in[2];
    const float* Wq    = (const float*)d_in[3];
    const float* bq    = (const float*)d_in[4];
    const float* Wk    = (const float*)d_in[5];
    const float* bk    = (const float*)d_in[6];
    const float* Wv    = (const float*)d_in[7];
    const float* bv    = (const float*)d_in[8];
    float* out = (float*)d_out;

    cudaFuncSetAttribute(qkv_kernel,    cudaFuncAttributeMaxDynamicSharedMemorySize, DSM2);
    cudaFuncSetAttribute(scores_kernel, cudaFuncAttributeMaxDynamicSharedMemorySize, DSM2);
    cudaFuncSetAttribute(av_kernel,     cudaFuncAttributeMaxDynamicSharedMemorySize, AV_DSM);

    ln_wconv_kernel<<<NTOK / 8 + 192, 256>>>(x, gamma, beta, Wq, Wk, Wv);
    qkv_kernel<<<dim3(NTOK / 128, C_ / 128, 3), 128, DSM2>>>(bq, bk, bv);
    scores_kernel<<<dim3(T_ / 128, T_ / 128, B_), 128, DSM2>>>();
    zv_kernel<<<NTOK / 8, 256>>>();
    av_kernel<<<dim3(T_ / 128, C_ / 128, B_), 128, AV_DSM>>>(x, out);
}

// round 17
// speedup vs baseline: 1.5113x; 1.5113x over previous
#include <cuda_runtime.h>
#include <cuda_bf16.h>
#include <cstdint>

#define B_   4
#define T_   4096
#define C_   256
#define NTOK (B_ * T_)   // 16384

typedef __nv_bfloat16 bf16;

// ---------------- scratch (static device arrays; no allocation) --------------
__device__ bf16  g_gn[NTOK * C_];
__device__ bf16  g_wq[C_ * C_], g_wk[C_ * C_], g_wv[C_ * C_];
__device__ bf16  g_q [NTOK * C_];
__device__ bf16  g_k [NTOK * C_];
__device__ bf16  g_v [NTOK * C_];
__device__ bf16  g_e [(size_t)B_ * T_ * T_];   // E: [b][t][s] natural
__device__ bf16  g_vp[NTOK * C_];              // V': [b][t][c] = V/Z_t
__device__ float g_zpart[32 * NTOK];           // [s_tile][token]

// ---------------- helpers ------------------------------------------------------
__device__ __forceinline__ uint32_t smem_u32(const void* p) {
    uint32_t a;
    asm("{ .reg .u64 t; cvta.to.shared.u64 t, %1; cvt.u32.u64 %0, t; }" : "=r"(a) : "l"(p));
    return a;
}
__device__ __forceinline__ void cp16(uint32_t dst, const void* src) {
    asm volatile("cp.async.cg.shared.global [%0], [%1], 16;" :: "r"(dst), "l"(src));
}
__device__ __forceinline__ void cp_commit() {
    asm volatile("cp.async.commit_group;" ::: "memory");
}
template <int N> __device__ __forceinline__ void cp_wait() {
    asm volatile("cp.async.wait_group %0;" :: "n"(N) : "memory");
}
__device__ __forceinline__ void mma_bf16(float c[4],
                                         uint32_t a0, uint32_t a1, uint32_t a2, uint32_t a3,
                                         uint32_t b0, uint32_t b1) {
    asm volatile(
        "mma.sync.aligned.m16n8k16.row.col.f32.bf16.bf16.f32 "
        "{%0,%1,%2,%3}, {%4,%5,%6,%7}, {%8,%9}, {%0,%1,%2,%3};"
        : "+f"(c[0]), "+f"(c[1]), "+f"(c[2]), "+f"(c[3])
        : "r"(a0), "r"(a1), "r"(a2), "r"(a3), "r"(b0), "r"(b1));
}
__device__ __forceinline__ void ldsm4(uint32_t& r0, uint32_t& r1, uint32_t& r2, uint32_t& r3,
                                      uint32_t addr) {
    asm volatile("ldmatrix.sync.aligned.m8n8.x4.shared.b16 {%0,%1,%2,%3}, [%4];"
                 : "=r"(r0), "=r"(r1), "=r"(r2), "=r"(r3) : "r"(addr));
}
__device__ __forceinline__ void ldsm4t(uint32_t& r0, uint32_t& r1, uint32_t& r2, uint32_t& r3,
                                       uint32_t addr) {
    asm volatile("ldmatrix.sync.aligned.m8n8.x4.trans.shared.b16 {%0,%1,%2,%3}, [%4];"
                 : "=r"(r0), "=r"(r1), "=r"(r2), "=r"(r3) : "r"(addr));
}
__device__ __forceinline__ void stsm4(uint32_t addr, uint32_t r0, uint32_t r1,
                                      uint32_t r2, uint32_t r3) {
    asm volatile("stmatrix.sync.aligned.m8n8.x4.shared.b16 [%0], {%1,%2,%3,%4};"
                 :: "r"(addr), "r"(r0), "r"(r1), "r"(r2), "r"(r3) : "memory");
}
__device__ __forceinline__ float ex2(float x) {
    float y; asm("ex2.approx.f32 %0, %1;" : "=f"(y) : "f"(x)); return y;
}
__device__ __forceinline__ uint32_t pack_bf16(float a, float b) {
    uint32_t lo = __bfloat16_as_ushort(__float2bfloat16(a));
    uint32_t hi = __bfloat16_as_ushort(__float2bfloat16(b));
    return lo | (hi << 16);
}

// ---- scores/qkv smem ([rows][72 bf16], 144 B stride) ------------------------
#define BOFF  18432u
#define STG   36864u
#define DSM2  73728
// ---- av smem: two [64 k][136 u16] tiles (272 B stride), 2 stages ------------
#define AV_VOFF  17408u
#define AV_STG   34816u
#define AV_DSM   69632

// exp(x/16) = 2^(x * 0.0625*log2(e))
#define EXP_SCALE 0.09016844f

// =================== LayerNorm: warp-per-token, no barriers ==================
__global__ void __launch_bounds__(256) ln_kernel(const float* __restrict__ x,
                                                 const float* __restrict__ gamma,
                                                 const float* __restrict__ beta) {
    const int warp = threadIdx.x >> 5;
    const int lane = threadIdx.x & 31;
    const int t = blockIdx.x * 8 + warp;
    const int c = lane * 8;
    const float* xr = x + (size_t)t * C_;

    float4 v0 = *(const float4*)&xr[c];
    float4 v1 = *(const float4*)&xr[c + 4];
    float s  = v0.x + v0.y + v0.z + v0.w + v1.x + v1.y + v1.z + v1.w;
    float sq = v0.x * v0.x + v0.y * v0.y + v0.z * v0.z + v0.w * v0.w
             + v1.x * v1.x + v1.y * v1.y + v1.z * v1.z + v1.w * v1.w;
    #pragma unroll
    for (int o = 16; o > 0; o >>= 1) {
        s  += __shfl_xor_sync(0xffffffffu, s,  o);
        sq += __shfl_xor_sync(0xffffffffu, sq, o);
    }
    float mu   = s * (1.f / C_);
    float var  = sq * (1.f / C_) - mu * mu;
    float rstd = rsqrtf(var + 1e-5f);

    float4 gm0 = *(const float4*)&gamma[c];
    float4 gm1 = *(const float4*)&gamma[c + 4];
    float4 bt0 = *(const float4*)&beta[c];
    float4 bt1 = *(const float4*)&beta[c + 4];

    uint4 o_;
    o_.x = pack_bf16((v0.x - mu) * rstd * gm0.x + bt0.x, (v0.y - mu) * rstd * gm0.y + bt0.y);
    o_.y = pack_bf16((v0.z - mu) * rstd * gm0.z + bt0.z, (v0.w - mu) * rstd * gm0.w + bt0.w);
    o_.z = pack_bf16((v1.x - mu) * rstd * gm1.x + bt1.x, (v1.y - mu) * rstd * gm1.y + bt1.y);
    o_.w = pack_bf16((v1.z - mu) * rstd * gm1.z + bt1.z, (v1.w - mu) * rstd * gm1.w + bt1.w);
    *(uint4*)&g_gn[(size_t)t * C_ + c] = o_;
}

// ======================= weight fp32 -> bf16 converter =======================
__global__ void __launch_bounds__(256) wconv_kernel(const float* __restrict__ Wq,
                                                    const float* __restrict__ Wk,
                                                    const float* __restrict__ Wv) {
    const float* src = (blockIdx.y == 0) ? Wq : (blockIdx.y == 1) ? Wk : Wv;
    bf16* dst = (blockIdx.y == 0) ? g_wq : (blockIdx.y == 1) ? g_wk : g_wv;
    int i = (blockIdx.x * 256 + threadIdx.x) * 4;
    float4 v = *(const float4*)&src[i];
    *(uint2*)&dst[i] = make_uint2(pack_bf16(v.x, v.y), pack_bf16(v.z, v.w));
}

// ====== QKV (bf16, 128 thr, 64x64 warp tiles, 2-stage single-sync) ===========
__global__ void __launch_bounds__(128, 3) qkv_kernel(const float* __restrict__ bq,
                                                     const float* __restrict__ bk,
                                                     const float* __restrict__ bv) {
    extern __shared__ char dsm[];
    const bf16* W; const float* bias; bf16* out;
    if (blockIdx.z == 0)      { W = g_wq; bias = bq; out = g_q; }
    else if (blockIdx.z == 1) { W = g_wk; bias = bk; out = g_k; }
    else                      { W = g_wv; bias = bv; out = g_v; }

    const int tid  = threadIdx.x;
    const int lane = tid & 31;
    const int wid  = tid >> 5;
    const int wm   = wid >> 1;
    const int wn   = wid & 1;
    const int m0   = blockIdx.x * 128;
    const int n0   = blockIdx.y * 128;

    float acc[4][8][4];
    #pragma unroll
    for (int mi = 0; mi < 4; mi++)
        #pragma unroll
        for (int ni = 0; ni < 8; ni++)
            #pragma unroll
            for (int r = 0; r < 4; r++) acc[mi][ni][r] = 0.f;

    const uint32_t sA = smem_u32(dsm);
    const uint32_t sB = sA + BOFF;

    const int arow = (lane & 7) + (lane & 8);
    const int acol = (lane & 16) ? 8 : 0;
    uint32_t aAddr[4];
    #pragma unroll
    for (int mi = 0; mi < 4; mi++)
        aAddr[mi] = sA + (uint32_t)(((wm * 64 + mi * 16 + arow) * 72 + acol) * 2);
    const int brow = (lane & 7) + ((lane & 16) ? 8 : 0);
    const int bcol = (lane & 8) ? 8 : 0;
    uint32_t bAddr[4];
    #pragma unroll
    for (int p = 0; p < 4; p++)
        bAddr[p] = sB + (uint32_t)(((wn * 64 + p * 16 + brow) * 72 + bcol) * 2);

    const int lrow = tid >> 3;          // 0..15
    const int lc8  = (tid & 7) * 8;

    auto issue_chunk = [&](int kc) {
        int kb = kc * 64;
        uint32_t so = (kc & 1) * STG;
        #pragma unroll
        for (int i = 0; i < 8; i++) {
            int row = lrow + i * 16;
            uint32_t d = so + (uint32_t)((row * 72 + lc8) * 2);
            cp16(sA + d, &g_gn[(size_t)(m0 + row) * C_ + kb + lc8]);
            cp16(sB + d, &W   [(size_t)(n0 + row) * C_ + kb + lc8]);
        }
        cp_commit();
    };

    issue_chunk(0);

    for (int kt = 0; kt < 4; kt++) {
        cp_wait<0>();
        __syncthreads();
        if (kt < 3) issue_chunk(kt + 1);

        const uint32_t so = (kt & 1) * STG;
        #pragma unroll
        for (int ks_i = 0; ks_i < 4; ks_i++) {
            const uint32_t koff = so + ks_i * 32;
            uint32_t a[4][4];
            #pragma unroll
            for (int mi = 0; mi < 4; mi++)
                ldsm4(a[mi][0], a[mi][1], a[mi][2], a[mi][3], aAddr[mi] + koff);
            #pragma unroll
            for (int p = 0; p < 4; p++) {
                uint32_t b0, b1, b2, b3;
                ldsm4(b0, b1, b2, b3, bAddr[p] + koff);
                #pragma unroll
                for (int mi = 0; mi < 4; mi++) {
                    mma_bf16(acc[mi][2 * p],     a[mi][0], a[mi][1], a[mi][2], a[mi][3], b0, b1);
                    mma_bf16(acc[mi][2 * p + 1], a[mi][0], a[mi][1], a[mi][2], a[mi][3], b2, b3);
                }
            }
        }
    }

    const int g = lane >> 2, tig = lane & 3;
    #pragma unroll
    for (int mi = 0; mi < 4; mi++) {
        int row = m0 + wm * 64 + mi * 16 + g;
        #pragma unroll
        for (int ni = 0; ni < 8; ni++) {
            int col = n0 + wn * 64 + ni * 8 + tig * 2;
            float bx = bias[col], by = bias[col + 1];
            *(uint32_t*)&out[(size_t)row * C_ + col] =
                pack_bf16(acc[mi][ni][0] + bx, acc[mi][ni][1] + by);
            *(uint32_t*)&out[(size_t)(row + 8) * C_ + col] =
                pack_bf16(acc[mi][ni][2] + bx, acc[mi][ni][3] + by);
        }
    }
}

// = scores (bf16, 128 thr, 64x64 warps, 1-sync) + ex2 + stmatrix E staging ====
__global__ void __launch_bounds__(128, 3) scores_kernel() {
    extern __shared__ char dsm[];
    __shared__ float rs[128];

    const int bz = blockIdx.z;
    const int t0 = blockIdx.x * 128;   // query rows
    const int s0 = blockIdx.y * 128;   // key cols
    const bf16* Q = g_q + (size_t)bz * T_ * C_;
    const bf16* K = g_k + (size_t)bz * T_ * C_;

    const int tid  = threadIdx.x;
    const int lane = tid & 31;
    const int wid  = tid >> 5;
    const int wm   = wid >> 1;
    const int wn   = wid & 1;
    if (tid < 128) rs[tid] = 0.f;

    float acc[4][8][4];
    #pragma unroll
    for (int mi = 0; mi < 4; mi++)
        #pragma unroll
        for (int ni = 0; ni < 8; ni++)
            #pragma unroll
            for (int r = 0; r < 4; r++) acc[mi][ni][r] = 0.f;

    const uint32_t sA = smem_u32(dsm);
    const uint32_t sB = sA + BOFF;

    const int arow = (lane & 7) + (lane & 8);
    const int acol = (lane & 16) ? 8 : 0;
    uint32_t aAddr[4];
    #pragma unroll
    for (int mi = 0; mi < 4; mi++)
        aAddr[mi] = sA + (uint32_t)(((wm * 64 + mi * 16 + arow) * 72 + acol) * 2);
    const int brow = (lane & 7) + ((lane & 16) ? 8 : 0);
    const int bcol = (lane & 8) ? 8 : 0;
    uint32_t bAddr[4];
    #pragma unroll
    for (int p = 0; p < 4; p++)
        bAddr[p] = sB + (uint32_t)(((wn * 64 + p * 16 + brow) * 72 + bcol) * 2);

    const int lrow = tid >> 3;          // 0..15
    const int lc8  = (tid & 7) * 8;

    auto issue_chunk = [&](int kc) {
        int kb = kc * 64;
        uint32_t so = (kc & 1) * STG;
        #pragma unroll
        for (int i = 0; i < 8; i++) {
            int row = lrow + i * 16;
            uint32_t d = so + (uint32_t)((row * 72 + lc8) * 2);
            cp16(sA + d, &Q[(size_t)(t0 + row) * C_ + kb + lc8]);
            cp16(sB + d, &K[(size_t)(s0 + row) * C_ + kb + lc8]);
        }
        cp_commit();
    };

    issue_chunk(0);

    for (int kt = 0; kt < 4; kt++) {
        cp_wait<0>();
        __syncthreads();
        if (kt < 3) issue_chunk(kt + 1);

        const uint32_t so = (kt & 1) * STG;
        #pragma unroll
        for (int ks_i = 0; ks_i < 4; ks_i++) {
            const uint32_t koff = so + ks_i * 32;
            uint32_t a[4][4];
            #pragma unroll
            for (int mi = 0; mi < 4; mi++)
                ldsm4(a[mi][0], a[mi][1], a[mi][2], a[mi][3], aAddr[mi] + koff);
            #pragma unroll
            for (int p = 0; p < 4; p++) {
                uint32_t b0, b1, b2, b3;
                ldsm4(b0, b1, b2, b3, bAddr[p] + koff);
                #pragma unroll
                for (int mi = 0; mi < 4; mi++) {
                    mma_bf16(acc[mi][2 * p],     a[mi][0], a[mi][1], a[mi][2], a[mi][3], b0, b1);
                    mma_bf16(acc[mi][2 * p + 1], a[mi][0], a[mi][1], a[mi][2], a[mi][3], b2, b3);
                }
            }
        }
    }

    const int g = lane >> 2, tig = lane & 3;

    // exp(score/16) via single-mul ex2
    #pragma unroll
    for (int mi = 0; mi < 4; mi++)
        #pragma unroll
        for (int ni = 0; ni < 8; ni++)
            #pragma unroll
            for (int r = 0; r < 4; r++)
                acc[mi][ni][r] = ex2(acc[mi][ni][r] * EXP_SCALE);

    #pragma unroll
    for (int mi = 0; mi < 4; mi++) {
        float s0v = 0.f, s1v = 0.f;
        #pragma unroll
        for (int ni = 0; ni < 8; ni++) {
            s0v += acc[mi][ni][0] + acc[mi][ni][1];
            s1v += acc[mi][ni][2] + acc[mi][ni][3];
        }
        s0v += __shfl_xor_sync(0xffffffffu, s0v, 1);
        s0v += __shfl_xor_sync(0xffffffffu, s0v, 2);
        s1v += __shfl_xor_sync(0xffffffffu, s1v, 1);
        s1v += __shfl_xor_sync(0xffffffffu, s1v, 2);
        if (tig == 0) {
            atomicAdd(&rs[wm * 64 + mi * 16 + g],     s0v);
            atomicAdd(&rs[wm * 64 + mi * 16 + g + 8], s1v);
        }
    }
    __syncthreads();   // mma/ldsm reads of dsm done + rowsums complete
    if (tid < 128)
        g_zpart[(size_t)blockIdx.y * NTOK + bz * T_ + t0 + tid] = rs[tid];

    // stage NATURAL bf16 tile via stmatrix: et[t_local 128][s_local 136]
    unsigned short* et = (unsigned short*)dsm;
    const uint32_t etB = smem_u32(et);
    const int m4 = lane >> 3;           // matrix index 0..3
    const uint32_t laneRow = (uint32_t)((m4 & 1) * 8 + (lane & 7));
    const uint32_t laneColHalf = (uint32_t)((m4 >> 1) * 8);
    #pragma unroll
    for (int mi = 0; mi < 4; mi++) {
        uint32_t rowBase = (uint32_t)(wm * 64 + mi * 16) + laneRow;
        #pragma unroll
        for (int njp = 0; njp < 4; njp++) {
            int ni = 2 * njp;
            uint32_t col = (uint32_t)(wn * 64 + njp * 16) + laneColHalf;
            uint32_t addr = etB + (rowBase * 136 + col) * 2;
            stsm4(addr,
                  pack_bf16(acc[mi][ni][0],     acc[mi][ni][1]),
                  pack_bf16(acc[mi][ni][2],     acc[mi][ni][3]),
                  pack_bf16(acc[mi][ni + 1][0], acc[mi][ni + 1][1]),
                  pack_bf16(acc[mi][ni + 1][2], acc[mi][ni + 1][3]));
        }
    }
    __syncthreads();
    // coalesced store E[b][t0+tl][s0 .. s0+127]
    #pragma unroll
    for (int i = 0; i < 16; i++) {
        int lin = tid + i * 128;
        int tl = lin >> 4, c8 = (lin & 15) * 8;
        uint4 d = *(uint4*)&et[(size_t)tl * 136 + c8];
        *(uint4*)&g_e[(size_t)(bz * T_ + t0 + tl) * T_ + s0 + c8] = d;
    }
}

// == zv (fused Z-reduce): one warp per token; V'[t][c] = V[t][c] / Z_t ========
__global__ void __launch_bounds__(256) zv_kernel() {
    const int warp = threadIdx.x >> 5;
    const int lane = threadIdx.x & 31;
    const int tok  = blockIdx.x * 8 + warp;

    float s = g_zpart[(size_t)lane * NTOK + tok];
    #pragma unroll
    for (int o = 16; o > 0; o >>= 1) s += __shfl_xor_sync(0xffffffffu, s, o);
    float zi = 1.f / s;

    const int c = lane * 8;
    uint4 raw = *(const uint4*)&g_v[(size_t)tok * C_ + c];
    const unsigned short* u = (const unsigned short*)&raw;
    uint4 outv;
    unsigned short* o = (unsigned short*)&outv;
    #pragma unroll
    for (int j = 0; j < 8; j++) {
        float f = __bfloat162float(__ushort_as_bfloat16(u[j])) * zi;
        o[j] = __bfloat16_as_ushort(__float2bfloat16(f));
    }
    *(uint4*)&g_vp[(size_t)tok * C_ + c] = outv;
}

// == AV: out[s,c] = x + Σ_t E[t,s]·V'[t,c]; both operands trans-ldsm ==========
__global__ void __launch_bounds__(128, 3) av_kernel(const float* __restrict__ x,
                                                    float* __restrict__ out) {
    extern __shared__ char dsm[];
    const int bz = blockIdx.z;
    const int s0 = blockIdx.x * 128;
    const int c0 = blockIdx.y * 128;
    const bf16* Ea = g_e  + (size_t)bz * T_ * T_;   // [t][s]
    const bf16* Va = g_vp + (size_t)bz * T_ * C_;   // [t][c]

    const int tid  = threadIdx.x;
    const int lane = tid & 31;
    const int wid  = tid >> 5;
    const int wm   = wid >> 1;    // s-half
    const int wn   = wid & 1;     // c-half

    float acc[4][8][4];
    #pragma unroll
    for (int mi = 0; mi < 4; mi++)
        #pragma unroll
        for (int ni = 0; ni < 8; ni++)
            #pragma unroll
            for (int r = 0; r < 4; r++) acc[mi][ni][r] = 0.f;

    const uint32_t sE = smem_u32(dsm);
    const uint32_t sV = sE + AV_VOFF;

    const int atrow = (lane & 7) + ((lane & 16) ? 8 : 0);
    const int atcol = (lane & 8) ? 8 : 0;
    uint32_t aAddr[4];
    #pragma unroll
    for (int mi = 0; mi < 4; mi++)
        aAddr[mi] = sE + (uint32_t)((atrow * 136 + wm * 64 + mi * 16 + atcol) * 2);
    const int btrow = (lane & 7) + ((lane & 8) ? 8 : 0);
    const int btcol = (lane & 16) ? 8 : 0;
    uint32_t bAddr[4];
    #pragma unroll
    for (int p = 0; p < 4; p++)
        bAddr[p] = sV + (uint32_t)((btrow * 136 + wn * 64 + p * 16 + btcol) * 2);

    const int lrow = tid >> 4;          // 0..7
    const int lc16 = (tid & 15) * 16;   // byte col

    auto issue_chunk = [&](int kc) {
        int kb = kc * 64;
        uint32_t so = (kc & 1) * AV_STG;
        #pragma unroll
        for (int i = 0; i < 8; i++) {
            int r = lrow + i * 8;
            uint32_t d = so + (uint32_t)(r * 272 + lc16);
            cp16(sE + d, &Ea[(size_t)(kb + r) * T_ + s0 + (lc16 >> 1)]);
            cp16(sV + d, &Va[(size_t)(kb + r) * C_ + c0 + (lc16 >> 1)]);
        }
        cp_commit();
    };

    issue_chunk(0);

    const int KT = T_ / 64;   // 64
    for (int kt = 0; kt < KT; kt++) {
        cp_wait<0>();
        __syncthreads();
        if (kt < KT - 1) issue_chunk(kt + 1);

        const uint32_t so = (kt & 1) * AV_STG;
        #pragma unroll
        for (int ks_i = 0; ks_i < 4; ks_i++) {
            const uint32_t koff = so + ks_i * 16 * 272;   // 16 k-rows
            uint32_t a[4][4];
            #pragma unroll
            for (int mi = 0; mi < 4; mi++)
                ldsm4t(a[mi][0], a[mi][1], a[mi][2], a[mi][3], aAddr[mi] + koff);
            #pragma unroll
            for (int p = 0; p < 4; p++) {
                uint32_t b0, b1, b2, b3;
                ldsm4t(b0, b1, b2, b3, bAddr[p] + koff);
                #pragma unroll
                for (int mi = 0; mi < 4; mi++) {
                    mma_bf16(acc[mi][2 * p],     a[mi][0], a[mi][1], a[mi][2], a[mi][3], b0, b1);
                    mma_bf16(acc[mi][2 * p + 1], a[mi][0], a[mi][1], a[mi][2], a[mi][3], b2, b3);
                }
            }
        }
    }

    const int g = lane >> 2, tig = lane & 3;
    #pragma unroll
    for (int mi = 0; mi < 4; mi++) {
        int s = s0 + wm * 64 + mi * 16 + g;
        size_t base0 = ((size_t)bz * T_ + s) * C_;
        size_t base1 = ((size_t)bz * T_ + s + 8) * C_;
        #pragma unroll
        for (int ni = 0; ni < 8; ni++) {
            int c = c0 + wn * 64 + ni * 8 + tig * 2;
            float2 x0 = *(const float2*)&x[base0 + c];
            float2 x1 = *(const float2*)&x[base1 + c];
            *(float2*)&out[base0 + c] = make_float2(x0.x + acc[mi][ni][0], x0.y + acc[mi][ni][1]);
            *(float2*)&out[base1 + c] = make_float2(x1.x + acc[mi][ni][2], x1.y + acc[mi][ni][3]);
        }
    }
}

// ================================ launch =====================================
extern "C" void kernel_launch(void* const* d_in, const int* in_sizes, int n_in,
                              void* d_out, int out_size) {
    const float* x     = (const float*)d_in[0];
    const float* gamma = (const float*)d_in[1];
    const float* beta  = (const float*)d_in[2];
    const float* Wq    = (const float*)d_in[3];
    const float* bq    = (const float*)d_in[4];
    const float* Wk    = (const float*)d_in[5];
    const float* bk    = (const float*)d_in[6];
    const float* Wv    = (const float*)d_in[7];
    const float* bv    = (const float*)d_in[8];
    float* out = (float*)d_out;

    cudaFuncSetAttribute(qkv_kernel,    cudaFuncAttributeMaxDynamicSharedMemorySize, DSM2);
    cudaFuncSetAttribute(scores_kernel, cudaFuncAttributeMaxDynamicSharedMemorySize, DSM2);
    cudaFuncSetAttribute(av_kernel,     cudaFuncAttributeMaxDynamicSharedMemorySize, AV_DSM);

    ln_kernel<<<NTOK / 8, 256>>>(x, gamma, beta);
    wconv_kernel<<<dim3(64, 3), 256>>>(Wq, Wk, Wv);
    qkv_kernel<<<dim3(NTOK / 128, C_ / 128, 3), 128, DSM2>>>(bq, bk, bv);
    scores_kernel<<<dim3(T_ / 128, T_ / 128, B_), 128, DSM2>>>();
    zv_kernel<<<NTOK / 8, 256>>>();
    av_kernel<<<dim3(T_ / 128, C_ / 128, B_), 128, AV_DSM>>>(x, out);
}